// round 8
// baseline (speedup 1.0000x reference)
#include <cuda_runtime.h>
#include <cuda_fp16.h>
#include <cstdint>
#include <math.h>

#define E_NUM 8
#define D_DIM 1024
#define H_DIM 1024
#define H2    2048
#define NTOK  2048
#define NPAIR 4096

// ----------------------------- scratch globals ------------------------------
__device__ int g_pairs[NPAIR];
__device__ int g_cnt[E_NUM];
__device__ int g_off[E_NUM];
__device__ __half g_x[(size_t)NTOK * D_DIM];                // by TOKEN
__device__ __half g_w1_hi[(size_t)E_NUM * D_DIM * H2];      // [E][k=D][n=2H]
__device__ __half g_w2_hi[(size_t)E_NUM * H_DIM * D_DIM];   // [E][k=H][n=D]
__device__ __half g_act[(size_t)NPAIR * H_DIM];             // by sorted SLOT
__device__ float g_ypair[(size_t)NPAIR * D_DIM];            // by pair id

// ------------------------------ helpers -------------------------------------
__device__ __forceinline__ uint32_t smem_u32(const void* p) {
    uint32_t a;
    asm("{ .reg .u64 t; cvta.to.shared.u64 t, %1; cvt.u32.u64 %0, t; }"
        : "=r"(a) : "l"(p));
    return a;
}
// bulk async copy gmem -> smem, completion via mbarrier complete_tx
__device__ __forceinline__ void bulk_cp(uint32_t dst, const void* src,
                                        uint32_t bytes, uint32_t mbar) {
    asm volatile(
        "cp.async.bulk.shared::cluster.global.mbarrier::complete_tx::bytes "
        "[%0], [%1], %2, [%3];"
        :: "r"(dst), "l"(src), "r"(bytes), "r"(mbar) : "memory");
}
__device__ __forceinline__ void mbar_init(uint32_t a, uint32_t cnt) {
    asm volatile("mbarrier.init.shared.b64 [%0], %1;" :: "r"(a), "r"(cnt) : "memory");
}
__device__ __forceinline__ void mbar_expect_tx(uint32_t a, uint32_t bytes) {
    asm volatile("mbarrier.arrive.expect_tx.shared.b64 _, [%0], %1;"
                 :: "r"(a), "r"(bytes) : "memory");
}
__device__ __forceinline__ void mbar_wait(uint32_t a, uint32_t parity) {
    asm volatile(
        "{\n\t.reg .pred P;\n"
        "WL_%=:\n\t"
        "mbarrier.try_wait.parity.acquire.cta.shared::cta.b64 P, [%0], %1, 0x989680;\n\t"
        "@P bra.uni WD_%=;\n\t"
        "bra.uni WL_%=;\n"
        "WD_%=:\n\t}"
        :: "r"(a), "r"(parity) : "memory");
}
__device__ __forceinline__ void ldsm4(uint32_t* r, uint32_t a) {
    asm volatile("ldmatrix.sync.aligned.m8n8.x4.shared.b16 {%0,%1,%2,%3}, [%4];"
                 : "=r"(r[0]), "=r"(r[1]), "=r"(r[2]), "=r"(r[3]) : "r"(a));
}
__device__ __forceinline__ void ldsm4t(uint32_t* r, uint32_t a) {
    asm volatile("ldmatrix.sync.aligned.m8n8.x4.trans.shared.b16 {%0,%1,%2,%3}, [%4];"
                 : "=r"(r[0]), "=r"(r[1]), "=r"(r[2]), "=r"(r[3]) : "r"(a));
}
__device__ __forceinline__ void mma16816(float* d, const uint32_t* a, const uint32_t* b) {
    asm volatile(
        "mma.sync.aligned.m16n8k16.row.col.f32.f16.f16.f32 "
        "{%0,%1,%2,%3}, {%4,%5,%6,%7}, {%8,%9}, {%0,%1,%2,%3};"
        : "+f"(d[0]), "+f"(d[1]), "+f"(d[2]), "+f"(d[3])
        : "r"(a[0]), "r"(a[1]), "r"(a[2]), "r"(a[3]), "r"(b[0]), "r"(b[1]));
}
__device__ __forceinline__ uint32_t pack_h2(__half a, __half b) {
    return ((uint32_t)__half_as_ushort(b) << 16) | (uint32_t)__half_as_ushort(a);
}
__device__ __forceinline__ float silu_mul(float h, float g) {
    return h * (g / (1.f + __expf(-g)));
}

// SMEM: rows_s[128] ints @0; mbar[3] u64 @512; stages @576.
// Stage: A [128m][32k] pitch 80 | B [32k][128n] pitch 272.  3 stages.
#define A_PITCH  80
#define B_PITCH  272
#define OFF_A    0
#define OFF_B    (128 * A_PITCH)
#define STAGE_SZ (128 * A_PITCH + 32 * B_PITCH)     // 18944
#define NSTAGE   3
#define HDR      576
#define SMEM_DYN (HDR + NSTAGE * STAGE_SZ)          // 57408
#define STAGE_BYTES 16384u                          // A 8KB + B 8KB payload

// ---------------------------------------------------------------------------
// Kernel 0: bucket pairs by expert (single CTA)
// ---------------------------------------------------------------------------
__global__ void bucket_kernel(const int* __restrict__ expert_idxs) {
    __shared__ int scnt[E_NUM];
    __shared__ int soff[E_NUM];
    __shared__ int spos[E_NUM];
    int tid = threadIdx.x;
    if (tid < E_NUM) scnt[tid] = 0;
    __syncthreads();
    for (int i = tid; i < NPAIR; i += blockDim.x)
        atomicAdd(&scnt[expert_idxs[i]], 1);
    __syncthreads();
    if (tid == 0) {
        int s = 0;
        for (int e = 0; e < E_NUM; e++) { soff[e] = s; spos[e] = s; s += scnt[e]; }
    }
    __syncthreads();
    for (int i = tid; i < NPAIR; i += blockDim.x) {
        int e = expert_idxs[i];
        int pos = atomicAdd(&spos[e], 1);
        g_pairs[pos] = i;
    }
    __syncthreads();
    if (tid < E_NUM) { g_cnt[tid] = scnt[tid]; g_off[tid] = soff[tid]; }
}

// ---------------------------------------------------------------------------
// Kernel 1: convert x by TOKEN to fp16
// ---------------------------------------------------------------------------
__global__ void conv_x_kernel(const float* __restrict__ x) {
    int tok = blockIdx.x;
    int t   = threadIdx.x;
    float4 v = ((const float4*)(x + (size_t)tok * D_DIM))[t];
    size_t o = (size_t)tok * D_DIM + t * 4;
    *(uint2*)(g_x + o) = make_uint2(
        pack_h2(__float2half_rn(v.x), __float2half_rn(v.y)),
        pack_h2(__float2half_rn(v.z), __float2half_rn(v.w)));
}

// ---------------------------------------------------------------------------
// Kernel 2a/2b: streaming convert W1/W2 fp32 -> fp16 (device-global dst)
// ---------------------------------------------------------------------------
__global__ void conv_w1_kernel(const float* __restrict__ W1) {
    const int total4 = E_NUM * D_DIM * H2 / 4;
    int idx = blockIdx.x * blockDim.x + threadIdx.x;
    if (idx >= total4) return;
    float4 v = ((const float4*)W1)[idx];
    uint2 o;
    o.x = pack_h2(__float2half_rn(v.x), __float2half_rn(v.y));
    o.y = pack_h2(__float2half_rn(v.z), __float2half_rn(v.w));
    *(uint2*)(g_w1_hi + (size_t)idx * 4) = o;
}

__global__ void conv_w2_kernel(const float* __restrict__ W2) {
    const int total4 = E_NUM * H_DIM * D_DIM / 4;
    int idx = blockIdx.x * blockDim.x + threadIdx.x;
    if (idx >= total4) return;
    float4 v = ((const float4*)W2)[idx];
    uint2 o;
    o.x = pack_h2(__float2half_rn(v.x), __float2half_rn(v.y));
    o.y = pack_h2(__float2half_rn(v.z), __float2half_rn(v.w));
    *(uint2*)(g_w2_hi + (size_t)idx * 4) = o;
}

// ---------------------------------------------------------------------------
// GEMM1 (mma.sync fp16, bulk-copy loader): act = h * silu(g)
//   CTA 128 rows x (64 h + 64 g cols). 8 warps = wm(4) x wc(2); warp 32m x 64c.
//   grid = (H/64, NPAIR/128, E)
// ---------------------------------------------------------------------------
__global__ void __launch_bounds__(256, 1) gemm1_mma() {
    extern __shared__ char smem[];
    const int e   = blockIdx.z;
    const int bn  = blockIdx.x;
    const int bm  = blockIdx.y;
    const int cnt = g_cnt[e];
    if (bm * 128 >= cnt) return;
    const int off = g_off[e];
    const int tid = threadIdx.x;
    const int wid = tid >> 5;
    const int l   = tid & 31;
    const int wm  = wid >> 1;
    const int wc  = wid & 1;

    int* rows_s = (int*)smem;
    const uint32_t smem_b = smem_u32(smem);
    const uint32_t mbar0  = smem_b + 512;
    const uint32_t sbase  = smem_b + HDR;

    if (tid < 128) {
        int m = bm * 128 + tid;
        rows_s[tid] = (m < cnt) ? (g_pairs[off + m] >> 1) : 0;
    }
    if (tid == 0) {
        mbar_init(mbar0, 1);
        mbar_init(mbar0 + 8, 1);
        mbar_init(mbar0 + 16, 1);
    }
    __syncthreads();

    uint32_t a_rel[2][2];
#pragma unroll
    for (int mt = 0; mt < 2; mt++)
#pragma unroll
        for (int kk = 0; kk < 2; kk++)
            a_rel[mt][kk] = (wm * 32 + mt * 16 + (l & 15)) * A_PITCH + kk * 32 + (l >> 4) * 16;

    uint32_t b_rel[4][2];
#pragma unroll
    for (int p = 0; p < 4; p++) {
        int colbase = (p < 2) ? (wc * 32 + p * 16) : (64 + wc * 32 + (p - 2) * 16);
#pragma unroll
        for (int kk = 0; kk < 2; kk++)
            b_rel[p][kk] = (kk * 16 + (l & 15)) * B_PITCH + (colbase + (l >> 4) * 8) * 2;
    }

    float acc[2][8][4];
#pragma unroll
    for (int mt = 0; mt < 2; mt++)
#pragma unroll
        for (int nt = 0; nt < 8; nt++)
#pragma unroll
            for (int i = 0; i < 4; i++) acc[mt][nt][i] = 0.f;

    // ---- bulk loader: 128 A-row copies (64B) + 64 B-segment copies (128B) ----
    auto load_stage = [&](int c, int slot) {
        const int kt = c * 32;
        const uint32_t st = sbase + slot * STAGE_SZ;
        const uint32_t mb = mbar0 + slot * 8;
        if (tid == 0) mbar_expect_tx(mb, STAGE_BYTES);
        if (tid < 128) {
            int r = tid;
            bulk_cp(st + OFF_A + r * A_PITCH,
                    g_x + (size_t)rows_s[r] * D_DIM + kt, 64, mb);
        } else if (tid < 192) {
            int j  = tid - 128;
            int r  = j >> 1;           // k-row 0..31
            int h2 = j & 1;            // 0 = h cols, 1 = g cols
            int gcol = (h2 == 0) ? (bn * 64) : (H_DIM + bn * 64);
            bulk_cp(st + OFF_B + r * B_PITCH + h2 * 128,
                    g_w1_hi + ((size_t)e * D_DIM + kt + r) * H2 + gcol, 128, mb);
        }
    };

    load_stage(0, 0);
    load_stage(1, 1);

    for (int c = 0; c < 32; c++) {
        const int slot = c % NSTAGE;
        if (c <= 29) load_stage(c + 2, (c + 2) % NSTAGE);
        mbar_wait(mbar0 + slot * 8, (c / NSTAGE) & 1);
        const uint32_t st = sbase + slot * STAGE_SZ;
#pragma unroll
        for (int kk = 0; kk < 2; kk++) {
            uint32_t ah[2][4], bf[4][4];
#pragma unroll
            for (int mt = 0; mt < 2; mt++)
                ldsm4(ah[mt], st + OFF_A + a_rel[mt][kk]);
#pragma unroll
            for (int p = 0; p < 4; p++)
                ldsm4t(bf[p], st + OFF_B + b_rel[p][kk]);
#pragma unroll
            for (int mt = 0; mt < 2; mt++)
#pragma unroll
                for (int nt = 0; nt < 8; nt++)
                    mma16816(acc[mt][nt], ah[mt], &bf[nt >> 1][(nt & 1) * 2]);
        }
        __syncthreads();
    }

    // ---- epilogue: pair h (nt) with g (nt+4), SiLU-GLU, store fp16 ----
#pragma unroll
    for (int mt = 0; mt < 2; mt++) {
        int m0 = bm * 128 + wm * 32 + mt * 16 + (l >> 2);
        int m1 = m0 + 8;
        bool v0 = (m0 < cnt), v1 = (m1 < cnt);
        size_t row0 = (size_t)(off + m0) * H_DIM;
        size_t row1 = (size_t)(off + m1) * H_DIM;
#pragma unroll
        for (int nt = 0; nt < 4; nt++) {
            int col = bn * 64 + wc * 32 + nt * 8 + 2 * (l & 3);
            float a0 = silu_mul(acc[mt][nt][0], acc[mt][nt + 4][0]);
            float a1 = silu_mul(acc[mt][nt][1], acc[mt][nt + 4][1]);
            float a2 = silu_mul(acc[mt][nt][2], acc[mt][nt + 4][2]);
            float a3 = silu_mul(acc[mt][nt][3], acc[mt][nt + 4][3]);
            if (v0)
                *(uint32_t*)(g_act + row0 + col) =
                    pack_h2(__float2half_rn(a0), __float2half_rn(a1));
            if (v1)
                *(uint32_t*)(g_act + row1 + col) =
                    pack_h2(__float2half_rn(a2), __float2half_rn(a3));
        }
    }
}

// ---------------------------------------------------------------------------
// GEMM2 (mma.sync fp16, bulk-copy loader): y_pair = (act @ W2) * p, scatter
//   CTA 128 x 128, warp 32m x 64n.  grid = (D/128, NPAIR/128, E)
// ---------------------------------------------------------------------------
__global__ void __launch_bounds__(256, 1) gemm2_mma(const float* __restrict__ expert_p) {
    extern __shared__ char smem[];
    const int e   = blockIdx.z;
    const int bn  = blockIdx.x;
    const int bm  = blockIdx.y;
    const int cnt = g_cnt[e];
    if (bm * 128 >= cnt) return;
    const int off = g_off[e];
    const int tid = threadIdx.x;
    const int wid = tid >> 5;
    const int l   = tid & 31;
    const int wm  = wid >> 1;
    const int wc  = wid & 1;

    const uint32_t smem_b = smem_u32(smem);
    const uint32_t mbar0  = smem_b + 512;
    const uint32_t sbase  = smem_b + HDR;

    if (tid == 0) {
        mbar_init(mbar0, 1);
        mbar_init(mbar0 + 8, 1);
        mbar_init(mbar0 + 16, 1);
    }
    __syncthreads();

    uint32_t a_rel[2][2], b_rel[4][2];
#pragma unroll
    for (int mt = 0; mt < 2; mt++)
#pragma unroll
        for (int kk = 0; kk < 2; kk++)
            a_rel[mt][kk] = (wm * 32 + mt * 16 + (l & 15)) * A_PITCH + kk * 32 + (l >> 4) * 16;
#pragma unroll
    for (int p = 0; p < 4; p++) {
        int colbase = wc * 64 + p * 16;
#pragma unroll
        for (int kk = 0; kk < 2; kk++)
            b_rel[p][kk] = (kk * 16 + (l & 15)) * B_PITCH + (colbase + (l >> 4) * 8) * 2;
    }

    float acc[2][8][4];
#pragma unroll
    for (int mt = 0; mt < 2; mt++)
#pragma unroll
        for (int nt = 0; nt < 8; nt++)
#pragma unroll
            for (int i = 0; i < 4; i++) acc[mt][nt][i] = 0.f;

    // ---- bulk loader: 128 A-row copies (64B) + 32 B-row copies (256B) ----
    auto load_stage = [&](int c, int slot) {
        const int kt = c * 32;
        const uint32_t st = sbase + slot * STAGE_SZ;
        const uint32_t mb = mbar0 + slot * 8;
        if (tid == 0) mbar_expect_tx(mb, STAGE_BYTES);
        if (tid < 128) {
            int r = tid;
            int gr = off + bm * 128 + r;
            if (gr > NPAIR - 1) gr = NPAIR - 1;
            bulk_cp(st + OFF_A + r * A_PITCH,
                    g_act + (size_t)gr * H_DIM + kt, 64, mb);
        } else if (tid < 160) {
            int r = tid - 128;        // k-row 0..31
            bulk_cp(st + OFF_B + r * B_PITCH,
                    g_w2_hi + ((size_t)e * H_DIM + kt + r) * D_DIM + bn * 128, 256, mb);
        }
    };

    load_stage(0, 0);
    load_stage(1, 1);

    for (int c = 0; c < 32; c++) {
        const int slot = c % NSTAGE;
        if (c <= 29) load_stage(c + 2, (c + 2) % NSTAGE);
        mbar_wait(mbar0 + slot * 8, (c / NSTAGE) & 1);
        const uint32_t st = sbase + slot * STAGE_SZ;
#pragma unroll
        for (int kk = 0; kk < 2; kk++) {
            uint32_t ah[2][4], bf[4][4];
#pragma unroll
            for (int mt = 0; mt < 2; mt++)
                ldsm4(ah[mt], st + OFF_A + a_rel[mt][kk]);
#pragma unroll
            for (int p = 0; p < 4; p++)
                ldsm4t(bf[p], st + OFF_B + b_rel[p][kk]);
#pragma unroll
            for (int mt = 0; mt < 2; mt++)
#pragma unroll
                for (int nt = 0; nt < 8; nt++)
                    mma16816(acc[mt][nt], ah[mt], &bf[nt >> 1][(nt & 1) * 2]);
        }
        __syncthreads();
    }

    // ---- epilogue: scale by gate prob, scatter rows by pair id ----
#pragma unroll
    for (int mt = 0; mt < 2; mt++) {
        int m0 = bm * 128 + wm * 32 + mt * 16 + (l >> 2);
        int m1 = m0 + 8;
        bool v0 = (m0 < cnt), v1 = (m1 < cnt);
        int   pid0 = 0, pid1 = 0;
        float pv0 = 0.f, pv1 = 0.f;
        if (v0) { pid0 = g_pairs[off + m0]; pv0 = expert_p[pid0]; }
        if (v1) { pid1 = g_pairs[off + m1]; pv1 = expert_p[pid1]; }
        float* dst0 = g_ypair + (size_t)pid0 * D_DIM;
        float* dst1 = g_ypair + (size_t)pid1 * D_DIM;
#pragma unroll
        for (int nt = 0; nt < 8; nt++) {
            int col = bn * 128 + wc * 64 + nt * 8 + 2 * (l & 3);
            if (v0) {
                float2 o = make_float2(acc[mt][nt][0] * pv0, acc[mt][nt][1] * pv0);
                *(float2*)(dst0 + col) = o;
            }
            if (v1) {
                float2 o = make_float2(acc[mt][nt][2] * pv1, acc[mt][nt][3] * pv1);
                *(float2*)(dst1 + col) = o;
            }
        }
    }
}

// ---------------------------------------------------------------------------
// Kernel 5: combine the K=2 slots of each token
// ---------------------------------------------------------------------------
__global__ void combine_kernel(float* __restrict__ out) {
    const int D4 = D_DIM / 4;
    int q = blockIdx.x * blockDim.x + threadIdx.x;
    if (q >= NTOK * D4) return;
    int t  = q / D4;
    int d4 = q - t * D4;
    const float4* yp = (const float4*)g_ypair;
    float4 a = yp[(size_t)(2 * t) * D4 + d4];
    float4 b = yp[(size_t)(2 * t + 1) * D4 + d4];
    float4 o;
    o.x = a.x + b.x; o.y = a.y + b.y; o.z = a.z + b.z; o.w = a.w + b.w;
    ((float4*)out)[q] = o;
}

// ---------------------------------------------------------------------------
extern "C" void kernel_launch(void* const* d_in, const int* in_sizes, int n_in,
                              void* d_out, int out_size) {
    const float* x    = (const float*)d_in[0];
    const float* ep   = (const float*)d_in[1];
    const int*   eidx = (const int*)  d_in[2];
    const float* W1   = (const float*)d_in[3];
    const float* W2   = (const float*)d_in[4];
    float*       out  = (float*)d_out;

    cudaFuncSetAttribute(gemm1_mma, cudaFuncAttributeMaxDynamicSharedMemorySize, SMEM_DYN);
    cudaFuncSetAttribute(gemm2_mma, cudaFuncAttributeMaxDynamicSharedMemorySize, SMEM_DYN);

    bucket_kernel<<<1, 512>>>(eidx);
    conv_x_kernel<<<NTOK, 256>>>(x);

    int w1_4 = E_NUM * D_DIM * H2 / 4;
    conv_w1_kernel<<<(w1_4 + 255) / 256, 256>>>(W1);
    int w2_4 = E_NUM * H_DIM * D_DIM / 4;
    conv_w2_kernel<<<(w2_4 + 255) / 256, 256>>>(W2);

    dim3 g1(H_DIM / 64, NPAIR / 128, E_NUM);    // (16, 32, 8)
    gemm1_mma<<<g1, 256, SMEM_DYN>>>();

    dim3 g2(D_DIM / 128, NPAIR / 128, E_NUM);   // (8, 32, 8)
    gemm2_mma<<<g2, 256, SMEM_DYN>>>(ep);

    int total4 = NTOK * (D_DIM / 4);
    combine_kernel<<<(total4 + 255) / 256, 256>>>(out);
}

// round 9
// speedup vs baseline: 2.0906x; 2.0906x over previous
#include <cuda_runtime.h>
#include <cuda_fp16.h>
#include <cstdint>
#include <math.h>

#define E_NUM 8
#define D_DIM 1024
#define H_DIM 1024
#define H2    2048
#define NTOK  2048
#define NPAIR 4096

// ----------------------------- scratch globals ------------------------------
__device__ int g_pairs[NPAIR];
__device__ int g_cnt[E_NUM];
__device__ int g_off[E_NUM];
__device__ __half g_x[(size_t)NTOK * D_DIM];                // by TOKEN
__device__ __half g_w1_hi[(size_t)E_NUM * D_DIM * H2];      // [E][k=D][n=2H]
__device__ __half g_w2_hi[(size_t)E_NUM * H_DIM * D_DIM];   // [E][k=H][n=D]
__device__ __half g_act[(size_t)NPAIR * H_DIM];             // by sorted SLOT
__device__ float g_ypair[(size_t)NPAIR * D_DIM];            // by pair id

// ------------------------------ helpers -------------------------------------
__device__ __forceinline__ uint32_t smem_u32(const void* p) {
    uint32_t a;
    asm("{ .reg .u64 t; cvta.to.shared.u64 t, %1; cvt.u32.u64 %0, t; }"
        : "=r"(a) : "l"(p));
    return a;
}
__device__ __forceinline__ void cp16(uint32_t dst, const void* src) {
    asm volatile("cp.async.cg.shared.global [%0], [%1], 16;"
                 :: "r"(dst), "l"(src) : "memory");
}
#define CP_COMMIT() asm volatile("cp.async.commit_group;" ::: "memory")
#define CP_WAIT(n)  asm volatile("cp.async.wait_group %0;" :: "n"(n) : "memory")

__device__ __forceinline__ void ldsm4(uint32_t* r, uint32_t a) {
    asm volatile("ldmatrix.sync.aligned.m8n8.x4.shared.b16 {%0,%1,%2,%3}, [%4];"
                 : "=r"(r[0]), "=r"(r[1]), "=r"(r[2]), "=r"(r[3]) : "r"(a));
}
__device__ __forceinline__ void ldsm4t(uint32_t* r, uint32_t a) {
    asm volatile("ldmatrix.sync.aligned.m8n8.x4.trans.shared.b16 {%0,%1,%2,%3}, [%4];"
                 : "=r"(r[0]), "=r"(r[1]), "=r"(r[2]), "=r"(r[3]) : "r"(a));
}
__device__ __forceinline__ void mma16816(float* d, const uint32_t* a, const uint32_t* b) {
    asm volatile(
        "mma.sync.aligned.m16n8k16.row.col.f32.f16.f16.f32 "
        "{%0,%1,%2,%3}, {%4,%5,%6,%7}, {%8,%9}, {%0,%1,%2,%3};"
        : "+f"(d[0]), "+f"(d[1]), "+f"(d[2]), "+f"(d[3])
        : "r"(a[0]), "r"(a[1]), "r"(a[2]), "r"(a[3]), "r"(b[0]), "r"(b[1]));
}
__device__ __forceinline__ uint32_t pack_h2(__half a, __half b) {
    return ((uint32_t)__half_as_ushort(b) << 16) | (uint32_t)__half_as_ushort(a);
}
__device__ __forceinline__ float silu_mul(float h, float g) {
    return h * (g / (1.f + __expf(-g)));
}

// SMEM: rows_s[128] ints @0; stages @512.
// Stage: A [128m][32k] pitch 80 | B [32k][128n] pitch 272.  3 stages.
#define A_PITCH  80
#define B_PITCH  272
#define OFF_A    0
#define OFF_B    (128 * A_PITCH)
#define STAGE_SZ (128 * A_PITCH + 32 * B_PITCH)     // 18944
#define NSTAGE   3
#define SMEM_DYN (512 + NSTAGE * STAGE_SZ)          // 57344 (x2 CTAs = 114.7KB/SM)

// ---------------------------------------------------------------------------
// Kernel 0: bucket pairs by expert (single CTA)
// ---------------------------------------------------------------------------
__global__ void bucket_kernel(const int* __restrict__ expert_idxs) {
    __shared__ int scnt[E_NUM];
    __shared__ int soff[E_NUM];
    __shared__ int spos[E_NUM];
    int tid = threadIdx.x;
    if (tid < E_NUM) scnt[tid] = 0;
    __syncthreads();
    for (int i = tid; i < NPAIR; i += blockDim.x)
        atomicAdd(&scnt[expert_idxs[i]], 1);
    __syncthreads();
    if (tid == 0) {
        int s = 0;
        for (int e = 0; e < E_NUM; e++) { soff[e] = s; spos[e] = s; s += scnt[e]; }
    }
    __syncthreads();
    for (int i = tid; i < NPAIR; i += blockDim.x) {
        int e = expert_idxs[i];
        int pos = atomicAdd(&spos[e], 1);
        g_pairs[pos] = i;
    }
    __syncthreads();
    if (tid < E_NUM) { g_cnt[tid] = scnt[tid]; g_off[tid] = soff[tid]; }
}

// ---------------------------------------------------------------------------
// Kernel 1: convert x by TOKEN to fp16
// ---------------------------------------------------------------------------
__global__ void conv_x_kernel(const float* __restrict__ x) {
    int tok = blockIdx.x;
    int t   = threadIdx.x;
    float4 v = ((const float4*)(x + (size_t)tok * D_DIM))[t];
    size_t o = (size_t)tok * D_DIM + t * 4;
    *(uint2*)(g_x + o) = make_uint2(
        pack_h2(__float2half_rn(v.x), __float2half_rn(v.y)),
        pack_h2(__float2half_rn(v.z), __float2half_rn(v.w)));
}

// ---------------------------------------------------------------------------
// Kernel 2a/2b: streaming convert W1/W2 fp32 -> fp16 (device-global dst)
// ---------------------------------------------------------------------------
__global__ void conv_w1_kernel(const float* __restrict__ W1) {
    const int total4 = E_NUM * D_DIM * H2 / 4;
    int idx = blockIdx.x * blockDim.x + threadIdx.x;
    if (idx >= total4) return;
    float4 v = ((const float4*)W1)[idx];
    uint2 o;
    o.x = pack_h2(__float2half_rn(v.x), __float2half_rn(v.y));
    o.y = pack_h2(__float2half_rn(v.z), __float2half_rn(v.w));
    *(uint2*)(g_w1_hi + (size_t)idx * 4) = o;
}

__global__ void conv_w2_kernel(const float* __restrict__ W2) {
    const int total4 = E_NUM * H_DIM * D_DIM / 4;
    int idx = blockIdx.x * blockDim.x + threadIdx.x;
    if (idx >= total4) return;
    float4 v = ((const float4*)W2)[idx];
    uint2 o;
    o.x = pack_h2(__float2half_rn(v.x), __float2half_rn(v.y));
    o.y = pack_h2(__float2half_rn(v.z), __float2half_rn(v.w));
    *(uint2*)(g_w2_hi + (size_t)idx * 4) = o;
}

// ---------------------------------------------------------------------------
// GEMM1 (mma.sync fp16, occ=2): act = h * silu(g)
//   CTA 128 rows x (64 h + 64 g cols). 8 warps = wm(4) x wc(2); warp 32m x 64c.
//   grid = (H/64, NPAIR/128, E)
// ---------------------------------------------------------------------------
__global__ void __launch_bounds__(256, 2) gemm1_mma() {
    extern __shared__ char smem[];
    const int e   = blockIdx.z;
    const int bn  = blockIdx.x;
    const int bm  = blockIdx.y;
    const int cnt = g_cnt[e];
    if (bm * 128 >= cnt) return;
    const int off = g_off[e];
    const int tid = threadIdx.x;
    const int wid = tid >> 5;
    const int l   = tid & 31;
    const int wm  = wid >> 1;
    const int wc  = wid & 1;

    int* rows_s = (int*)smem;
    const uint32_t sbase = smem_u32(smem) + 512;

    if (tid < 128) {
        int m = bm * 128 + tid;
        rows_s[tid] = (m < cnt) ? (g_pairs[off + m] >> 1) : 0;
    }
    __syncthreads();

    uint32_t a_rel[2][2];
#pragma unroll
    for (int mt = 0; mt < 2; mt++)
#pragma unroll
        for (int kk = 0; kk < 2; kk++)
            a_rel[mt][kk] = (wm * 32 + mt * 16 + (l & 15)) * A_PITCH + kk * 32 + (l >> 4) * 16;

    uint32_t b_rel[4][2];
#pragma unroll
    for (int p = 0; p < 4; p++) {
        int colbase = (p < 2) ? (wc * 32 + p * 16) : (64 + wc * 32 + (p - 2) * 16);
#pragma unroll
        for (int kk = 0; kk < 2; kk++)
            b_rel[p][kk] = (kk * 16 + (l & 15)) * B_PITCH + (colbase + (l >> 4) * 8) * 2;
    }

    float acc[2][8][4];
#pragma unroll
    for (int mt = 0; mt < 2; mt++)
#pragma unroll
        for (int nt = 0; nt < 8; nt++)
#pragma unroll
            for (int i = 0; i < 4; i++) acc[mt][nt][i] = 0.f;

    auto load_stage = [&](int c, int buf) {
        const int kt = c * 32;
        const uint32_t st = sbase + buf * STAGE_SZ;
        // A: 512 chunks of 16B
#pragma unroll
        for (int i = 0; i < 2; i++) {
            int q = tid + i * 256;
            int r = q >> 2, ch = q & 3;
            cp16(st + OFF_A + r * A_PITCH + ch * 16,
                 g_x + (size_t)rows_s[r] * D_DIM + kt + ch * 8);
        }
        // B: 512 chunks; cols 0-63 h @ bn*64, 64-127 g @ H+bn*64
#pragma unroll
        for (int i = 0; i < 2; i++) {
            int q = tid + i * 256;
            int r = q >> 4, ch = q & 15;
            int gcol = (ch < 8) ? (bn * 64 + ch * 8) : (H_DIM + bn * 64 + (ch - 8) * 8);
            cp16(st + OFF_B + r * B_PITCH + ch * 16,
                 g_w1_hi + ((size_t)e * D_DIM + kt + r) * H2 + gcol);
        }
        CP_COMMIT();
    };

    load_stage(0, 0);
    load_stage(1, 1);

    for (int c = 0; c < 32; c++) {
        const int buf = c % NSTAGE;
        if (c < 30) { load_stage(c + 2, (c + 2) % NSTAGE); CP_WAIT(2); }
        else if (c == 30) { CP_WAIT(1); }
        else { CP_WAIT(0); }
        __syncthreads();
        const uint32_t st = sbase + buf * STAGE_SZ;
#pragma unroll
        for (int kk = 0; kk < 2; kk++) {
            uint32_t ah[2][4], bf[4][4];
#pragma unroll
            for (int mt = 0; mt < 2; mt++)
                ldsm4(ah[mt], st + OFF_A + a_rel[mt][kk]);
#pragma unroll
            for (int p = 0; p < 4; p++)
                ldsm4t(bf[p], st + OFF_B + b_rel[p][kk]);
#pragma unroll
            for (int mt = 0; mt < 2; mt++)
#pragma unroll
                for (int nt = 0; nt < 8; nt++)
                    mma16816(acc[mt][nt], ah[mt], &bf[nt >> 1][(nt & 1) * 2]);
        }
        __syncthreads();
    }

    // ---- epilogue: pair h (nt) with g (nt+4), SiLU-GLU, store fp16 ----
#pragma unroll
    for (int mt = 0; mt < 2; mt++) {
        int m0 = bm * 128 + wm * 32 + mt * 16 + (l >> 2);
        int m1 = m0 + 8;
        bool v0 = (m0 < cnt), v1 = (m1 < cnt);
        size_t row0 = (size_t)(off + m0) * H_DIM;
        size_t row1 = (size_t)(off + m1) * H_DIM;
#pragma unroll
        for (int nt = 0; nt < 4; nt++) {
            int col = bn * 64 + wc * 32 + nt * 8 + 2 * (l & 3);
            float a0 = silu_mul(acc[mt][nt][0], acc[mt][nt + 4][0]);
            float a1 = silu_mul(acc[mt][nt][1], acc[mt][nt + 4][1]);
            float a2 = silu_mul(acc[mt][nt][2], acc[mt][nt + 4][2]);
            float a3 = silu_mul(acc[mt][nt][3], acc[mt][nt + 4][3]);
            if (v0)
                *(uint32_t*)(g_act + row0 + col) =
                    pack_h2(__float2half_rn(a0), __float2half_rn(a1));
            if (v1)
                *(uint32_t*)(g_act + row1 + col) =
                    pack_h2(__float2half_rn(a2), __float2half_rn(a3));
        }
    }
}

// ---------------------------------------------------------------------------
// GEMM2 (mma.sync fp16, occ=2): y_pair = (act @ W2) * p, scatter
//   CTA 128 x 128, warp 32m x 64n.  grid = (D/128, NPAIR/128, E)
// ---------------------------------------------------------------------------
__global__ void __launch_bounds__(256, 2) gemm2_mma(const float* __restrict__ expert_p) {
    extern __shared__ char smem[];
    const int e   = blockIdx.z;
    const int bn  = blockIdx.x;
    const int bm  = blockIdx.y;
    const int cnt = g_cnt[e];
    if (bm * 128 >= cnt) return;
    const int off = g_off[e];
    const int tid = threadIdx.x;
    const int wid = tid >> 5;
    const int l   = tid & 31;
    const int wm  = wid >> 1;
    const int wc  = wid & 1;

    const uint32_t sbase = smem_u32(smem) + 512;

    uint32_t a_rel[2][2], b_rel[4][2];
#pragma unroll
    for (int mt = 0; mt < 2; mt++)
#pragma unroll
        for (int kk = 0; kk < 2; kk++)
            a_rel[mt][kk] = (wm * 32 + mt * 16 + (l & 15)) * A_PITCH + kk * 32 + (l >> 4) * 16;
#pragma unroll
    for (int p = 0; p < 4; p++) {
        int colbase = wc * 64 + p * 16;
#pragma unroll
        for (int kk = 0; kk < 2; kk++)
            b_rel[p][kk] = (kk * 16 + (l & 15)) * B_PITCH + (colbase + (l >> 4) * 8) * 2;
    }

    float acc[2][8][4];
#pragma unroll
    for (int mt = 0; mt < 2; mt++)
#pragma unroll
        for (int nt = 0; nt < 8; nt++)
#pragma unroll
            for (int i = 0; i < 4; i++) acc[mt][nt][i] = 0.f;

    auto load_stage = [&](int c, int buf) {
        const int kt = c * 32;
        const uint32_t st = sbase + buf * STAGE_SZ;
#pragma unroll
        for (int i = 0; i < 2; i++) {
            int q = tid + i * 256;
            int r = q >> 2, ch = q & 3;
            int gr = off + bm * 128 + r;
            if (gr > NPAIR - 1) gr = NPAIR - 1;
            cp16(st + OFF_A + r * A_PITCH + ch * 16,
                 g_act + (size_t)gr * H_DIM + kt + ch * 8);
        }
#pragma unroll
        for (int i = 0; i < 2; i++) {
            int q = tid + i * 256;
            int r = q >> 4, ch = q & 15;
            cp16(st + OFF_B + r * B_PITCH + ch * 16,
                 g_w2_hi + ((size_t)e * H_DIM + kt + r) * D_DIM + bn * 128 + ch * 8);
        }
        CP_COMMIT();
    };

    load_stage(0, 0);
    load_stage(1, 1);

    for (int c = 0; c < 32; c++) {
        const int buf = c % NSTAGE;
        if (c < 30) { load_stage(c + 2, (c + 2) % NSTAGE); CP_WAIT(2); }
        else if (c == 30) { CP_WAIT(1); }
        else { CP_WAIT(0); }
        __syncthreads();
        const uint32_t st = sbase + buf * STAGE_SZ;
#pragma unroll
        for (int kk = 0; kk < 2; kk++) {
            uint32_t ah[2][4], bf[4][4];
#pragma unroll
            for (int mt = 0; mt < 2; mt++)
                ldsm4(ah[mt], st + OFF_A + a_rel[mt][kk]);
#pragma unroll
            for (int p = 0; p < 4; p++)
                ldsm4t(bf[p], st + OFF_B + b_rel[p][kk]);
#pragma unroll
            for (int mt = 0; mt < 2; mt++)
#pragma unroll
                for (int nt = 0; nt < 8; nt++)
                    mma16816(acc[mt][nt], ah[mt], &bf[nt >> 1][(nt & 1) * 2]);
        }
        __syncthreads();
    }

    // ---- epilogue: scale by gate prob, scatter rows by pair id ----
#pragma unroll
    for (int mt = 0; mt < 2; mt++) {
        int m0 = bm * 128 + wm * 32 + mt * 16 + (l >> 2);
        int m1 = m0 + 8;
        bool v0 = (m0 < cnt), v1 = (m1 < cnt);
        int   pid0 = 0, pid1 = 0;
        float pv0 = 0.f, pv1 = 0.f;
        if (v0) { pid0 = g_pairs[off + m0]; pv0 = expert_p[pid0]; }
        if (v1) { pid1 = g_pairs[off + m1]; pv1 = expert_p[pid1]; }
        float* dst0 = g_ypair + (size_t)pid0 * D_DIM;
        float* dst1 = g_ypair + (size_t)pid1 * D_DIM;
#pragma unroll
        for (int nt = 0; nt < 8; nt++) {
            int col = bn * 128 + wc * 64 + nt * 8 + 2 * (l & 3);
            if (v0) {
                float2 o = make_float2(acc[mt][nt][0] * pv0, acc[mt][nt][1] * pv0);
                *(float2*)(dst0 + col) = o;
            }
            if (v1) {
                float2 o = make_float2(acc[mt][nt][2] * pv1, acc[mt][nt][3] * pv1);
                *(float2*)(dst1 + col) = o;
            }
        }
    }
}

// ---------------------------------------------------------------------------
// Kernel 5: combine the K=2 slots of each token
// ---------------------------------------------------------------------------
__global__ void combine_kernel(float* __restrict__ out) {
    const int D4 = D_DIM / 4;
    int q = blockIdx.x * blockDim.x + threadIdx.x;
    if (q >= NTOK * D4) return;
    int t  = q / D4;
    int d4 = q - t * D4;
    const float4* yp = (const float4*)g_ypair;
    float4 a = yp[(size_t)(2 * t) * D4 + d4];
    float4 b = yp[(size_t)(2 * t + 1) * D4 + d4];
    float4 o;
    o.x = a.x + b.x; o.y = a.y + b.y; o.z = a.z + b.z; o.w = a.w + b.w;
    ((float4*)out)[q] = o;
}

// ---------------------------------------------------------------------------
extern "C" void kernel_launch(void* const* d_in, const int* in_sizes, int n_in,
                              void* d_out, int out_size) {
    const float* x    = (const float*)d_in[0];
    const float* ep   = (const float*)d_in[1];
    const int*   eidx = (const int*)  d_in[2];
    const float* W1   = (const float*)d_in[3];
    const float* W2   = (const float*)d_in[4];
    float*       out  = (float*)d_out;

    cudaFuncSetAttribute(gemm1_mma, cudaFuncAttributeMaxDynamicSharedMemorySize, SMEM_DYN);
    cudaFuncSetAttribute(gemm2_mma, cudaFuncAttributeMaxDynamicSharedMemorySize, SMEM_DYN);

    bucket_kernel<<<1, 512>>>(eidx);
    conv_x_kernel<<<NTOK, 256>>>(x);

    int w1_4 = E_NUM * D_DIM * H2 / 4;
    conv_w1_kernel<<<(w1_4 + 255) / 256, 256>>>(W1);
    int w2_4 = E_NUM * H_DIM * D_DIM / 4;
    conv_w2_kernel<<<(w2_4 + 255) / 256, 256>>>(W2);

    dim3 g1(H_DIM / 64, NPAIR / 128, E_NUM);    // (16, 32, 8)
    gemm1_mma<<<g1, 256, SMEM_DYN>>>();

    dim3 g2(D_DIM / 128, NPAIR / 128, E_NUM);   // (8, 32, 8)
    gemm2_mma<<<g2, 256, SMEM_DYN>>>(ep);

    int total4 = NTOK * (D_DIM / 4);
    combine_kernel<<<(total4 + 255) / 256, 256>>>(out);
}

// round 10
// speedup vs baseline: 2.1626x; 1.0345x over previous
#include <cuda_runtime.h>
#include <cuda_fp16.h>
#include <cstdint>
#include <math.h>

#define E_NUM 8
#define D_DIM 1024
#define H_DIM 1024
#define H2    2048
#define NTOK  2048
#define NPAIR 4096

// ----------------------------- scratch globals ------------------------------
__device__ int g_pairs[NPAIR];
__device__ int g_cnt[E_NUM];
__device__ int g_off[E_NUM];
__device__ __half g_x[(size_t)NTOK * D_DIM];                // by TOKEN
__device__ __half g_w1_hi[(size_t)E_NUM * D_DIM * H2];      // [E][k=D][n=2H]
__device__ __half g_w2_hi[(size_t)E_NUM * H_DIM * D_DIM];   // [E][k=H][n=D]
__device__ __half g_act[(size_t)NPAIR * H_DIM];             // by sorted SLOT

// ------------------------------ helpers -------------------------------------
__device__ __forceinline__ uint32_t smem_u32(const void* p) {
    uint32_t a;
    asm("{ .reg .u64 t; cvta.to.shared.u64 t, %1; cvt.u32.u64 %0, t; }"
        : "=r"(a) : "l"(p));
    return a;
}
__device__ __forceinline__ void cp16(uint32_t dst, const void* src) {
    asm volatile("cp.async.cg.shared.global [%0], [%1], 16;"
                 :: "r"(dst), "l"(src) : "memory");
}
#define CP_COMMIT() asm volatile("cp.async.commit_group;" ::: "memory")
#define CP_WAIT(n)  asm volatile("cp.async.wait_group %0;" :: "n"(n) : "memory")

__device__ __forceinline__ void ldsm4(uint32_t* r, uint32_t a) {
    asm volatile("ldmatrix.sync.aligned.m8n8.x4.shared.b16 {%0,%1,%2,%3}, [%4];"
                 : "=r"(r[0]), "=r"(r[1]), "=r"(r[2]), "=r"(r[3]) : "r"(a));
}
__device__ __forceinline__ void ldsm4t(uint32_t* r, uint32_t a) {
    asm volatile("ldmatrix.sync.aligned.m8n8.x4.trans.shared.b16 {%0,%1,%2,%3}, [%4];"
                 : "=r"(r[0]), "=r"(r[1]), "=r"(r[2]), "=r"(r[3]) : "r"(a));
}
__device__ __forceinline__ void mma16816(float* d, const uint32_t* a, const uint32_t* b) {
    asm volatile(
        "mma.sync.aligned.m16n8k16.row.col.f32.f16.f16.f32 "
        "{%0,%1,%2,%3}, {%4,%5,%6,%7}, {%8,%9}, {%0,%1,%2,%3};"
        : "+f"(d[0]), "+f"(d[1]), "+f"(d[2]), "+f"(d[3])
        : "r"(a[0]), "r"(a[1]), "r"(a[2]), "r"(a[3]), "r"(b[0]), "r"(b[1]));
}
__device__ __forceinline__ uint32_t pack_h2(__half a, __half b) {
    return ((uint32_t)__half_as_ushort(b) << 16) | (uint32_t)__half_as_ushort(a);
}
__device__ __forceinline__ float silu_mul(float h, float g) {
    return h * (g / (1.f + __expf(-g)));
}

// SMEM: rows_s[128] ints @0; stages @512.
// Stage: A [128m][32k] pitch 80 | B [32k][128n] pitch 272.  4 stages.
#define A_PITCH  80
#define B_PITCH  272
#define OFF_A    0
#define OFF_B    (128 * A_PITCH)
#define STAGE_SZ (128 * A_PITCH + 32 * B_PITCH)     // 18944
#define NSTAGE   4
#define SMEM_DYN (512 + NSTAGE * STAGE_SZ)          // 76288 (x2 CTAs = 152.6KB/SM)

// ---------------------------------------------------------------------------
// Kernel 0: bucket pairs by expert (single CTA)
// ---------------------------------------------------------------------------
__global__ void bucket_kernel(const int* __restrict__ expert_idxs) {
    __shared__ int scnt[E_NUM];
    __shared__ int soff[E_NUM];
    __shared__ int spos[E_NUM];
    int tid = threadIdx.x;
    if (tid < E_NUM) scnt[tid] = 0;
    __syncthreads();
    for (int i = tid; i < NPAIR; i += blockDim.x)
        atomicAdd(&scnt[expert_idxs[i]], 1);
    __syncthreads();
    if (tid == 0) {
        int s = 0;
        for (int e = 0; e < E_NUM; e++) { soff[e] = s; spos[e] = s; s += scnt[e]; }
    }
    __syncthreads();
    for (int i = tid; i < NPAIR; i += blockDim.x) {
        int e = expert_idxs[i];
        int pos = atomicAdd(&spos[e], 1);
        g_pairs[pos] = i;
    }
    __syncthreads();
    if (tid < E_NUM) { g_cnt[tid] = scnt[tid]; g_off[tid] = soff[tid]; }
}

// ---------------------------------------------------------------------------
// Kernel 1: zero the output (poisoned by harness; atomics accumulate into it)
// ---------------------------------------------------------------------------
__global__ void zero_out_kernel(float* __restrict__ out) {
    int q = blockIdx.x * blockDim.x + threadIdx.x;
    ((float4*)out)[q] = make_float4(0.f, 0.f, 0.f, 0.f);
}

// ---------------------------------------------------------------------------
// Kernel 2: convert x by TOKEN to fp16 (8 floats / thread)
// ---------------------------------------------------------------------------
__global__ void conv_x_kernel(const float* __restrict__ x) {
    int idx = blockIdx.x * blockDim.x + threadIdx.x;   // one per 8 floats
    const float4* src = (const float4*)x + (size_t)idx * 2;
    float4 a = src[0], b = src[1];
    uint4 o;
    o.x = pack_h2(__float2half_rn(a.x), __float2half_rn(a.y));
    o.y = pack_h2(__float2half_rn(a.z), __float2half_rn(a.w));
    o.z = pack_h2(__float2half_rn(b.x), __float2half_rn(b.y));
    o.w = pack_h2(__float2half_rn(b.z), __float2half_rn(b.w));
    *(uint4*)(g_x + (size_t)idx * 8) = o;
}

// ---------------------------------------------------------------------------
// Kernel 3a/3b: streaming convert W1/W2 fp32 -> fp16 (8 floats / thread)
// ---------------------------------------------------------------------------
__global__ void conv_w1_kernel(const float* __restrict__ W1) {
    int idx = blockIdx.x * blockDim.x + threadIdx.x;
    const float4* src = (const float4*)W1 + (size_t)idx * 2;
    float4 a = src[0], b = src[1];
    uint4 o;
    o.x = pack_h2(__float2half_rn(a.x), __float2half_rn(a.y));
    o.y = pack_h2(__float2half_rn(a.z), __float2half_rn(a.w));
    o.z = pack_h2(__float2half_rn(b.x), __float2half_rn(b.y));
    o.w = pack_h2(__float2half_rn(b.z), __float2half_rn(b.w));
    *(uint4*)(g_w1_hi + (size_t)idx * 8) = o;
}

__global__ void conv_w2_kernel(const float* __restrict__ W2) {
    int idx = blockIdx.x * blockDim.x + threadIdx.x;
    const float4* src = (const float4*)W2 + (size_t)idx * 2;
    float4 a = src[0], b = src[1];
    uint4 o;
    o.x = pack_h2(__float2half_rn(a.x), __float2half_rn(a.y));
    o.y = pack_h2(__float2half_rn(a.z), __float2half_rn(a.w));
    o.z = pack_h2(__float2half_rn(b.x), __float2half_rn(b.y));
    o.w = pack_h2(__float2half_rn(b.z), __float2half_rn(b.w));
    *(uint4*)(g_w2_hi + (size_t)idx * 8) = o;
}

// ---------------------------------------------------------------------------
// GEMM1 (mma.sync fp16, occ=2, 4-stage): act = h * silu(g)
//   CTA 128 rows x (64 h + 64 g cols). 8 warps = wm(4) x wc(2); warp 32m x 64c.
//   grid = (H/64, NPAIR/128, E)
// ---------------------------------------------------------------------------
__global__ void __launch_bounds__(256, 2) gemm1_mma() {
    extern __shared__ char smem[];
    const int e   = blockIdx.z;
    const int bn  = blockIdx.x;
    const int bm  = blockIdx.y;
    const int cnt = g_cnt[e];
    if (bm * 128 >= cnt) return;
    const int off = g_off[e];
    const int tid = threadIdx.x;
    const int wid = tid >> 5;
    const int l   = tid & 31;
    const int wm  = wid >> 1;
    const int wc  = wid & 1;

    int* rows_s = (int*)smem;
    const uint32_t sbase = smem_u32(smem) + 512;

    if (tid < 128) {
        int m = bm * 128 + tid;
        rows_s[tid] = (m < cnt) ? (g_pairs[off + m] >> 1) : 0;
    }
    __syncthreads();

    uint32_t a_rel[2][2];
#pragma unroll
    for (int mt = 0; mt < 2; mt++)
#pragma unroll
        for (int kk = 0; kk < 2; kk++)
            a_rel[mt][kk] = (wm * 32 + mt * 16 + (l & 15)) * A_PITCH + kk * 32 + (l >> 4) * 16;

    uint32_t b_rel[4][2];
#pragma unroll
    for (int p = 0; p < 4; p++) {
        int colbase = (p < 2) ? (wc * 32 + p * 16) : (64 + wc * 32 + (p - 2) * 16);
#pragma unroll
        for (int kk = 0; kk < 2; kk++)
            b_rel[p][kk] = (kk * 16 + (l & 15)) * B_PITCH + (colbase + (l >> 4) * 8) * 2;
    }

    float acc[2][8][4];
#pragma unroll
    for (int mt = 0; mt < 2; mt++)
#pragma unroll
        for (int nt = 0; nt < 8; nt++)
#pragma unroll
            for (int i = 0; i < 4; i++) acc[mt][nt][i] = 0.f;

    auto load_stage = [&](int c, int buf) {
        const int kt = c * 32;
        const uint32_t st = sbase + buf * STAGE_SZ;
#pragma unroll
        for (int i = 0; i < 2; i++) {
            int q = tid + i * 256;
            int r = q >> 2, ch = q & 3;
            cp16(st + OFF_A + r * A_PITCH + ch * 16,
                 g_x + (size_t)rows_s[r] * D_DIM + kt + ch * 8);
        }
#pragma unroll
        for (int i = 0; i < 2; i++) {
            int q = tid + i * 256;
            int r = q >> 4, ch = q & 15;
            int gcol = (ch < 8) ? (bn * 64 + ch * 8) : (H_DIM + bn * 64 + (ch - 8) * 8);
            cp16(st + OFF_B + r * B_PITCH + ch * 16,
                 g_w1_hi + ((size_t)e * D_DIM + kt + r) * H2 + gcol);
        }
        CP_COMMIT();
    };

    load_stage(0, 0);
    load_stage(1, 1);
    load_stage(2, 2);

    for (int c = 0; c < 32; c++) {
        const int buf = c % NSTAGE;
        if (c < 29) { load_stage(c + 3, (c + 3) % NSTAGE); CP_WAIT(3); }
        else if (c == 29) { CP_WAIT(2); }
        else if (c == 30) { CP_WAIT(1); }
        else { CP_WAIT(0); }
        __syncthreads();
        const uint32_t st = sbase + buf * STAGE_SZ;
#pragma unroll
        for (int kk = 0; kk < 2; kk++) {
            uint32_t ah[2][4], bf[4][4];
#pragma unroll
            for (int mt = 0; mt < 2; mt++)
                ldsm4(ah[mt], st + OFF_A + a_rel[mt][kk]);
#pragma unroll
            for (int p = 0; p < 4; p++)
                ldsm4t(bf[p], st + OFF_B + b_rel[p][kk]);
#pragma unroll
            for (int mt = 0; mt < 2; mt++)
#pragma unroll
                for (int nt = 0; nt < 8; nt++)
                    mma16816(acc[mt][nt], ah[mt], &bf[nt >> 1][(nt & 1) * 2]);
        }
        __syncthreads();
    }

    // ---- epilogue: pair h (nt) with g (nt+4), SiLU-GLU, store fp16 ----
#pragma unroll
    for (int mt = 0; mt < 2; mt++) {
        int m0 = bm * 128 + wm * 32 + mt * 16 + (l >> 2);
        int m1 = m0 + 8;
        bool v0 = (m0 < cnt), v1 = (m1 < cnt);
        size_t row0 = (size_t)(off + m0) * H_DIM;
        size_t row1 = (size_t)(off + m1) * H_DIM;
#pragma unroll
        for (int nt = 0; nt < 4; nt++) {
            int col = bn * 64 + wc * 32 + nt * 8 + 2 * (l & 3);
            float a0 = silu_mul(acc[mt][nt][0], acc[mt][nt + 4][0]);
            float a1 = silu_mul(acc[mt][nt][1], acc[mt][nt + 4][1]);
            float a2 = silu_mul(acc[mt][nt][2], acc[mt][nt + 4][2]);
            float a3 = silu_mul(acc[mt][nt][3], acc[mt][nt + 4][3]);
            if (v0)
                *(uint32_t*)(g_act + row0 + col) =
                    pack_h2(__float2half_rn(a0), __float2half_rn(a1));
            if (v1)
                *(uint32_t*)(g_act + row1 + col) =
                    pack_h2(__float2half_rn(a2), __float2half_rn(a3));
        }
    }
}

// ---------------------------------------------------------------------------
// GEMM2 (mma.sync fp16, occ=2, 4-stage): out += (act @ W2) * p  (atomic)
//   CTA 128 x 128, warp 32m x 64n.  grid = (D/128, NPAIR/128, E)
//   Exactly 2 fp32 contributions per out element; fp add is commutative,
//   so the atomic accumulation is order-independent -> deterministic.
// ---------------------------------------------------------------------------
__global__ void __launch_bounds__(256, 2) gemm2_mma(const float* __restrict__ expert_p,
                                                    float* __restrict__ out) {
    extern __shared__ char smem[];
    const int e   = blockIdx.z;
    const int bn  = blockIdx.x;
    const int bm  = blockIdx.y;
    const int cnt = g_cnt[e];
    if (bm * 128 >= cnt) return;
    const int off = g_off[e];
    const int tid = threadIdx.x;
    const int wid = tid >> 5;
    const int l   = tid & 31;
    const int wm  = wid >> 1;
    const int wc  = wid & 1;

    const uint32_t sbase = smem_u32(smem) + 512;

    uint32_t a_rel[2][2], b_rel[4][2];
#pragma unroll
    for (int mt = 0; mt < 2; mt++)
#pragma unroll
        for (int kk = 0; kk < 2; kk++)
            a_rel[mt][kk] = (wm * 32 + mt * 16 + (l & 15)) * A_PITCH + kk * 32 + (l >> 4) * 16;
#pragma unroll
    for (int p = 0; p < 4; p++) {
        int colbase = wc * 64 + p * 16;
#pragma unroll
        for (int kk = 0; kk < 2; kk++)
            b_rel[p][kk] = (kk * 16 + (l & 15)) * B_PITCH + (colbase + (l >> 4) * 8) * 2;
    }

    float acc[2][8][4];
#pragma unroll
    for (int mt = 0; mt < 2; mt++)
#pragma unroll
        for (int nt = 0; nt < 8; nt++)
#pragma unroll
            for (int i = 0; i < 4; i++) acc[mt][nt][i] = 0.f;

    auto load_stage = [&](int c, int buf) {
        const int kt = c * 32;
        const uint32_t st = sbase + buf * STAGE_SZ;
#pragma unroll
        for (int i = 0; i < 2; i++) {
            int q = tid + i * 256;
            int r = q >> 2, ch = q & 3;
            int gr = off + bm * 128 + r;
            if (gr > NPAIR - 1) gr = NPAIR - 1;
            cp16(st + OFF_A + r * A_PITCH + ch * 16,
                 g_act + (size_t)gr * H_DIM + kt + ch * 8);
        }
#pragma unroll
        for (int i = 0; i < 2; i++) {
            int q = tid + i * 256;
            int r = q >> 4, ch = q & 15;
            cp16(st + OFF_B + r * B_PITCH + ch * 16,
                 g_w2_hi + ((size_t)e * H_DIM + kt + r) * D_DIM + bn * 128 + ch * 8);
        }
        CP_COMMIT();
    };

    load_stage(0, 0);
    load_stage(1, 1);
    load_stage(2, 2);

    for (int c = 0; c < 32; c++) {
        const int buf = c % NSTAGE;
        if (c < 29) { load_stage(c + 3, (c + 3) % NSTAGE); CP_WAIT(3); }
        else if (c == 29) { CP_WAIT(2); }
        else if (c == 30) { CP_WAIT(1); }
        else { CP_WAIT(0); }
        __syncthreads();
        const uint32_t st = sbase + buf * STAGE_SZ;
#pragma unroll
        for (int kk = 0; kk < 2; kk++) {
            uint32_t ah[2][4], bf[4][4];
#pragma unroll
            for (int mt = 0; mt < 2; mt++)
                ldsm4(ah[mt], st + OFF_A + a_rel[mt][kk]);
#pragma unroll
            for (int p = 0; p < 4; p++)
                ldsm4t(bf[p], st + OFF_B + b_rel[p][kk]);
#pragma unroll
            for (int mt = 0; mt < 2; mt++)
#pragma unroll
                for (int nt = 0; nt < 8; nt++)
                    mma16816(acc[mt][nt], ah[mt], &bf[nt >> 1][(nt & 1) * 2]);
        }
        __syncthreads();
    }

    // ---- epilogue: scale by gate prob, atomically accumulate into out ----
#pragma unroll
    for (int mt = 0; mt < 2; mt++) {
        int m0 = bm * 128 + wm * 32 + mt * 16 + (l >> 2);
        int m1 = m0 + 8;
        bool v0 = (m0 < cnt), v1 = (m1 < cnt);
        int   pid0 = 0, pid1 = 0;
        float pv0 = 0.f, pv1 = 0.f;
        if (v0) { pid0 = g_pairs[off + m0]; pv0 = expert_p[pid0]; }
        if (v1) { pid1 = g_pairs[off + m1]; pv1 = expert_p[pid1]; }
        float* dst0 = out + (size_t)(pid0 >> 1) * D_DIM;
        float* dst1 = out + (size_t)(pid1 >> 1) * D_DIM;
#pragma unroll
        for (int nt = 0; nt < 8; nt++) {
            int col = bn * 128 + wc * 64 + nt * 8 + 2 * (l & 3);
            if (v0) {
                atomicAdd(dst0 + col,     acc[mt][nt][0] * pv0);
                atomicAdd(dst0 + col + 1, acc[mt][nt][1] * pv0);
            }
            if (v1) {
                atomicAdd(dst1 + col,     acc[mt][nt][2] * pv1);
                atomicAdd(dst1 + col + 1, acc[mt][nt][3] * pv1);
            }
        }
    }
}

// ---------------------------------------------------------------------------
extern "C" void kernel_launch(void* const* d_in, const int* in_sizes, int n_in,
                              void* d_out, int out_size) {
    const float* x    = (const float*)d_in[0];
    const float* ep   = (const float*)d_in[1];
    const int*   eidx = (const int*)  d_in[2];
    const float* W1   = (const float*)d_in[3];
    const float* W2   = (const float*)d_in[4];
    float*       out  = (float*)d_out;

    cudaFuncSetAttribute(gemm1_mma, cudaFuncAttributeMaxDynamicSharedMemorySize, SMEM_DYN);
    cudaFuncSetAttribute(gemm2_mma, cudaFuncAttributeMaxDynamicSharedMemorySize, SMEM_DYN);

    bucket_kernel<<<1, 512>>>(eidx);
    zero_out_kernel<<<(NTOK * D_DIM / 4) / 256, 256>>>(out);

    int x8 = NTOK * D_DIM / 8;
    conv_x_kernel<<<x8 / 256, 256>>>(x);
    int w1_8 = E_NUM * D_DIM * H2 / 8;
    conv_w1_kernel<<<w1_8 / 256, 256>>>(W1);
    int w2_8 = E_NUM * H_DIM * D_DIM / 8;
    conv_w2_kernel<<<w2_8 / 256, 256>>>(W2);

    dim3 g1(H_DIM / 64, NPAIR / 128, E_NUM);    // (16, 32, 8)
    gemm1_mma<<<g1, 256, SMEM_DYN>>>();

    dim3 g2(D_DIM / 128, NPAIR / 128, E_NUM);   // (8, 32, 8)
    gemm2_mma<<<g2, 256, SMEM_DYN>>>(ep, out);
}

// round 11
// speedup vs baseline: 2.2640x; 1.0469x over previous
#include <cuda_runtime.h>
#include <cuda_fp16.h>
#include <cstdint>
#include <math.h>

#define E_NUM 8
#define D_DIM 1024
#define H_DIM 1024
#define H2    2048
#define NTOK  2048
#define NPAIR 4096

// ----------------------------- scratch globals ------------------------------
__device__ int g_pairs[NPAIR];
__device__ int g_cnt[E_NUM];
__device__ int g_off[E_NUM];
__device__ __half g_x[(size_t)NTOK * D_DIM];                // by TOKEN
__device__ __half g_w1_hi[(size_t)E_NUM * D_DIM * H2];      // [E][k=D][n=2H]
__device__ __half g_w2_hi[(size_t)E_NUM * H_DIM * D_DIM];   // [E][k=H][n=D]
__device__ __half g_act[(size_t)NPAIR * H_DIM];             // by sorted SLOT

// ------------------------------ helpers -------------------------------------
__device__ __forceinline__ uint32_t smem_u32(const void* p) {
    uint32_t a;
    asm("{ .reg .u64 t; cvta.to.shared.u64 t, %1; cvt.u32.u64 %0, t; }"
        : "=r"(a) : "l"(p));
    return a;
}
__device__ __forceinline__ void cp16(uint32_t dst, const void* src) {
    asm volatile("cp.async.cg.shared.global [%0], [%1], 16;"
                 :: "r"(dst), "l"(src) : "memory");
}
#define CP_COMMIT() asm volatile("cp.async.commit_group;" ::: "memory")
#define CP_WAIT(n)  asm volatile("cp.async.wait_group %0;" :: "n"(n) : "memory")

__device__ __forceinline__ void ldsm4(uint32_t* r, uint32_t a) {
    asm volatile("ldmatrix.sync.aligned.m8n8.x4.shared.b16 {%0,%1,%2,%3}, [%4];"
                 : "=r"(r[0]), "=r"(r[1]), "=r"(r[2]), "=r"(r[3]) : "r"(a));
}
__device__ __forceinline__ void ldsm4t(uint32_t* r, uint32_t a) {
    asm volatile("ldmatrix.sync.aligned.m8n8.x4.trans.shared.b16 {%0,%1,%2,%3}, [%4];"
                 : "=r"(r[0]), "=r"(r[1]), "=r"(r[2]), "=r"(r[3]) : "r"(a));
}
__device__ __forceinline__ void mma16816(float* d, const uint32_t* a, const uint32_t* b) {
    asm volatile(
        "mma.sync.aligned.m16n8k16.row.col.f32.f16.f16.f32 "
        "{%0,%1,%2,%3}, {%4,%5,%6,%7}, {%8,%9}, {%0,%1,%2,%3};"
        : "+f"(d[0]), "+f"(d[1]), "+f"(d[2]), "+f"(d[3])
        : "r"(a[0]), "r"(a[1]), "r"(a[2]), "r"(a[3]), "r"(b[0]), "r"(b[1]));
}
__device__ __forceinline__ uint32_t pack_h2(__half a, __half b) {
    return ((uint32_t)__half_as_ushort(b) << 16) | (uint32_t)__half_as_ushort(a);
}
__device__ __forceinline__ float silu_mul(float h, float g) {
    return h * (g / (1.f + __expf(-g)));
}

// SMEM: rows_s[128] ints @0; stages @512.
// Stage (K-chunk 64): A [128m][64k] pitch 144 | B [64k][128n] pitch 272. 3 stages.
#define A_PITCH  144
#define B_PITCH  272
#define OFF_A    0
#define OFF_B    (128 * A_PITCH)
#define STAGE_SZ (128 * A_PITCH + 64 * B_PITCH)     // 35840
#define NSTAGE   3
#define SMEM_DYN (512 + NSTAGE * STAGE_SZ)          // 108032 (x2 CTAs = 216KB/SM)
#define KCH      64
#define NITER    (D_DIM / KCH)                      // 16 (same for H_DIM)

// ---------------------------------------------------------------------------
// Kernel 0: bucket pairs by expert (single CTA)
// ---------------------------------------------------------------------------
__global__ void bucket_kernel(const int* __restrict__ expert_idxs) {
    __shared__ int scnt[E_NUM];
    __shared__ int soff[E_NUM];
    __shared__ int spos[E_NUM];
    int tid = threadIdx.x;
    if (tid < E_NUM) scnt[tid] = 0;
    __syncthreads();
    for (int i = tid; i < NPAIR; i += blockDim.x)
        atomicAdd(&scnt[expert_idxs[i]], 1);
    __syncthreads();
    if (tid == 0) {
        int s = 0;
        for (int e = 0; e < E_NUM; e++) { soff[e] = s; spos[e] = s; s += scnt[e]; }
    }
    __syncthreads();
    for (int i = tid; i < NPAIR; i += blockDim.x) {
        int e = expert_idxs[i];
        int pos = atomicAdd(&spos[e], 1);
        g_pairs[pos] = i;
    }
    __syncthreads();
    if (tid < E_NUM) { g_cnt[tid] = scnt[tid]; g_off[tid] = soff[tid]; }
}

// ---------------------------------------------------------------------------
// Kernel 1: zero the output (poisoned by harness; atomics accumulate into it)
// ---------------------------------------------------------------------------
__global__ void zero_out_kernel(float* __restrict__ out) {
    int q = blockIdx.x * blockDim.x + threadIdx.x;
    ((float4*)out)[q] = make_float4(0.f, 0.f, 0.f, 0.f);
}

// ---------------------------------------------------------------------------
// Kernel 2: convert x by TOKEN to fp16 (8 floats / thread)
// ---------------------------------------------------------------------------
__global__ void conv_x_kernel(const float* __restrict__ x) {
    int idx = blockIdx.x * blockDim.x + threadIdx.x;
    const float4* src = (const float4*)x + (size_t)idx * 2;
    float4 a = src[0], b = src[1];
    uint4 o;
    o.x = pack_h2(__float2half_rn(a.x), __float2half_rn(a.y));
    o.y = pack_h2(__float2half_rn(a.z), __float2half_rn(a.w));
    o.z = pack_h2(__float2half_rn(b.x), __float2half_rn(b.y));
    o.w = pack_h2(__float2half_rn(b.z), __float2half_rn(b.w));
    *(uint4*)(g_x + (size_t)idx * 8) = o;
}

// ---------------------------------------------------------------------------
// Kernel 3a/3b: streaming convert W1/W2 fp32 -> fp16 (8 floats / thread)
// ---------------------------------------------------------------------------
__global__ void conv_w1_kernel(const float* __restrict__ W1) {
    int idx = blockIdx.x * blockDim.x + threadIdx.x;
    const float4* src = (const float4*)W1 + (size_t)idx * 2;
    float4 a = src[0], b = src[1];
    uint4 o;
    o.x = pack_h2(__float2half_rn(a.x), __float2half_rn(a.y));
    o.y = pack_h2(__float2half_rn(a.z), __float2half_rn(a.w));
    o.z = pack_h2(__float2half_rn(b.x), __float2half_rn(b.y));
    o.w = pack_h2(__float2half_rn(b.z), __float2half_rn(b.w));
    *(uint4*)(g_w1_hi + (size_t)idx * 8) = o;
}

__global__ void conv_w2_kernel(const float* __restrict__ W2) {
    int idx = blockIdx.x * blockDim.x + threadIdx.x;
    const float4* src = (const float4*)W2 + (size_t)idx * 2;
    float4 a = src[0], b = src[1];
    uint4 o;
    o.x = pack_h2(__float2half_rn(a.x), __float2half_rn(a.y));
    o.y = pack_h2(__float2half_rn(a.z), __float2half_rn(a.w));
    o.z = pack_h2(__float2half_rn(b.x), __float2half_rn(b.y));
    o.w = pack_h2(__float2half_rn(b.z), __float2half_rn(b.w));
    *(uint4*)(g_w2_hi + (size_t)idx * 8) = o;
}

// ---------------------------------------------------------------------------
// GEMM1 (mma.sync fp16, occ=2, K-chunk 64, 3-stage): act = h * silu(g)
//   CTA 128 rows x (64 h + 64 g cols). 8 warps = wm(4) x wc(2); warp 32m x 64c.
//   grid = (H/64, NPAIR/128, E)
// ---------------------------------------------------------------------------
__global__ void __launch_bounds__(256, 2) gemm1_mma() {
    extern __shared__ char smem[];
    const int e   = blockIdx.z;
    const int bn  = blockIdx.x;
    const int bm  = blockIdx.y;
    const int cnt = g_cnt[e];
    if (bm * 128 >= cnt) return;
    const int off = g_off[e];
    const int tid = threadIdx.x;
    const int wid = tid >> 5;
    const int l   = tid & 31;
    const int wm  = wid >> 1;
    const int wc  = wid & 1;

    int* rows_s = (int*)smem;
    const uint32_t sbase = smem_u32(smem) + 512;

    if (tid < 128) {
        int m = bm * 128 + tid;
        rows_s[tid] = (m < cnt) ? (g_pairs[off + m] >> 1) : 0;
    }
    __syncthreads();

    // fragment address bases (kk offsets added in loop)
    uint32_t a_base[2];
#pragma unroll
    for (int mt = 0; mt < 2; mt++)
        a_base[mt] = (wm * 32 + mt * 16 + (l & 15)) * A_PITCH + (l >> 4) * 16;
    uint32_t b_base[4];
#pragma unroll
    for (int p = 0; p < 4; p++) {
        int colbase = (p < 2) ? (wc * 32 + p * 16) : (64 + wc * 32 + (p - 2) * 16);
        b_base[p] = (l & 15) * B_PITCH + (colbase + (l >> 4) * 8) * 2;
    }

    float acc[2][8][4];
#pragma unroll
    for (int mt = 0; mt < 2; mt++)
#pragma unroll
        for (int nt = 0; nt < 8; nt++)
#pragma unroll
            for (int i = 0; i < 4; i++) acc[mt][nt][i] = 0.f;

    auto load_stage = [&](int c, int buf) {
        const int kt = c * KCH;
        const uint32_t st = sbase + buf * STAGE_SZ;
        // A: 128 rows x 128B = 1024 cp16
#pragma unroll
        for (int i = 0; i < 4; i++) {
            int q = tid + i * 256;
            int r = q >> 3, ch = q & 7;
            cp16(st + OFF_A + r * A_PITCH + ch * 16,
                 g_x + (size_t)rows_s[r] * D_DIM + kt + ch * 8);
        }
        // B: 64 k-rows x 256B = 1024 cp16; ch<8 -> h cols, ch>=8 -> g cols
#pragma unroll
        for (int i = 0; i < 4; i++) {
            int q = tid + i * 256;
            int r = q >> 4, ch = q & 15;
            int gcol = (ch < 8) ? (bn * 64 + ch * 8) : (H_DIM + bn * 64 + (ch - 8) * 8);
            cp16(st + OFF_B + r * B_PITCH + ch * 16,
                 g_w1_hi + ((size_t)e * D_DIM + kt + r) * H2 + gcol);
        }
        CP_COMMIT();
    };

    load_stage(0, 0);
    load_stage(1, 1);

    for (int c = 0; c < NITER; c++) {
        const int buf = c % NSTAGE;
        if (c < NITER - 2) { load_stage(c + 2, (c + 2) % NSTAGE); CP_WAIT(2); }
        else if (c == NITER - 2) { CP_WAIT(1); }
        else { CP_WAIT(0); }
        __syncthreads();
        const uint32_t st = sbase + buf * STAGE_SZ;
#pragma unroll
        for (int kk = 0; kk < 4; kk++) {
            uint32_t ah[2][4], bf[4][4];
#pragma unroll
            for (int mt = 0; mt < 2; mt++)
                ldsm4(ah[mt], st + OFF_A + a_base[mt] + kk * 32);
#pragma unroll
            for (int p = 0; p < 4; p++)
                ldsm4t(bf[p], st + OFF_B + b_base[p] + kk * (16 * B_PITCH));
#pragma unroll
            for (int mt = 0; mt < 2; mt++)
#pragma unroll
                for (int nt = 0; nt < 8; nt++)
                    mma16816(acc[mt][nt], ah[mt], &bf[nt >> 1][(nt & 1) * 2]);
        }
        __syncthreads();
    }

    // ---- epilogue: pair h (nt) with g (nt+4), SiLU-GLU, store fp16 ----
#pragma unroll
    for (int mt = 0; mt < 2; mt++) {
        int m0 = bm * 128 + wm * 32 + mt * 16 + (l >> 2);
        int m1 = m0 + 8;
        bool v0 = (m0 < cnt), v1 = (m1 < cnt);
        size_t row0 = (size_t)(off + m0) * H_DIM;
        size_t row1 = (size_t)(off + m1) * H_DIM;
#pragma unroll
        for (int nt = 0; nt < 4; nt++) {
            int col = bn * 64 + wc * 32 + nt * 8 + 2 * (l & 3);
            float a0 = silu_mul(acc[mt][nt][0], acc[mt][nt + 4][0]);
            float a1 = silu_mul(acc[mt][nt][1], acc[mt][nt + 4][1]);
            float a2 = silu_mul(acc[mt][nt][2], acc[mt][nt + 4][2]);
            float a3 = silu_mul(acc[mt][nt][3], acc[mt][nt + 4][3]);
            if (v0)
                *(uint32_t*)(g_act + row0 + col) =
                    pack_h2(__float2half_rn(a0), __float2half_rn(a1));
            if (v1)
                *(uint32_t*)(g_act + row1 + col) =
                    pack_h2(__float2half_rn(a2), __float2half_rn(a3));
        }
    }
}

// ---------------------------------------------------------------------------
// GEMM2 (mma.sync fp16, occ=2, K-chunk 64, 3-stage): out += (act @ W2) * p
//   CTA 128 x 128, warp 32m x 64n.  grid = (D/128, NPAIR/128, E)
//   Exactly 2 fp32 contributions per out element -> order-independent.
// ---------------------------------------------------------------------------
__global__ void __launch_bounds__(256, 2) gemm2_mma(const float* __restrict__ expert_p,
                                                    float* __restrict__ out) {
    extern __shared__ char smem[];
    const int e   = blockIdx.z;
    const int bn  = blockIdx.x;
    const int bm  = blockIdx.y;
    const int cnt = g_cnt[e];
    if (bm * 128 >= cnt) return;
    const int off = g_off[e];
    const int tid = threadIdx.x;
    const int wid = tid >> 5;
    const int l   = tid & 31;
    const int wm  = wid >> 1;
    const int wc  = wid & 1;

    const uint32_t sbase = smem_u32(smem) + 512;

    uint32_t a_base[2];
#pragma unroll
    for (int mt = 0; mt < 2; mt++)
        a_base[mt] = (wm * 32 + mt * 16 + (l & 15)) * A_PITCH + (l >> 4) * 16;
    uint32_t b_base[4];
#pragma unroll
    for (int p = 0; p < 4; p++) {
        int colbase = wc * 64 + p * 16;
        b_base[p] = (l & 15) * B_PITCH + (colbase + (l >> 4) * 8) * 2;
    }

    float acc[2][8][4];
#pragma unroll
    for (int mt = 0; mt < 2; mt++)
#pragma unroll
        for (int nt = 0; nt < 8; nt++)
#pragma unroll
            for (int i = 0; i < 4; i++) acc[mt][nt][i] = 0.f;

    auto load_stage = [&](int c, int buf) {
        const int kt = c * KCH;
        const uint32_t st = sbase + buf * STAGE_SZ;
#pragma unroll
        for (int i = 0; i < 4; i++) {
            int q = tid + i * 256;
            int r = q >> 3, ch = q & 7;
            int gr = off + bm * 128 + r;
            if (gr > NPAIR - 1) gr = NPAIR - 1;
            cp16(st + OFF_A + r * A_PITCH + ch * 16,
                 g_act + (size_t)gr * H_DIM + kt + ch * 8);
        }
#pragma unroll
        for (int i = 0; i < 4; i++) {
            int q = tid + i * 256;
            int r = q >> 4, ch = q & 15;
            cp16(st + OFF_B + r * B_PITCH + ch * 16,
                 g_w2_hi + ((size_t)e * H_DIM + kt + r) * D_DIM + bn * 128 + ch * 8);
        }
        CP_COMMIT();
    };

    load_stage(0, 0);
    load_stage(1, 1);

    for (int c = 0; c < NITER; c++) {
        const int buf = c % NSTAGE;
        if (c < NITER - 2) { load_stage(c + 2, (c + 2) % NSTAGE); CP_WAIT(2); }
        else if (c == NITER - 2) { CP_WAIT(1); }
        else { CP_WAIT(0); }
        __syncthreads();
        const uint32_t st = sbase + buf * STAGE_SZ;
#pragma unroll
        for (int kk = 0; kk < 4; kk++) {
            uint32_t ah[2][4], bf[4][4];
#pragma unroll
            for (int mt = 0; mt < 2; mt++)
                ldsm4(ah[mt], st + OFF_A + a_base[mt] + kk * 32);
#pragma unroll
            for (int p = 0; p < 4; p++)
                ldsm4t(bf[p], st + OFF_B + b_base[p] + kk * (16 * B_PITCH));
#pragma unroll
            for (int mt = 0; mt < 2; mt++)
#pragma unroll
                for (int nt = 0; nt < 8; nt++)
                    mma16816(acc[mt][nt], ah[mt], &bf[nt >> 1][(nt & 1) * 2]);
        }
        __syncthreads();
    }

    // ---- epilogue: scale by gate prob, atomically accumulate into out ----
#pragma unroll
    for (int mt = 0; mt < 2; mt++) {
        int m0 = bm * 128 + wm * 32 + mt * 16 + (l >> 2);
        int m1 = m0 + 8;
        bool v0 = (m0 < cnt), v1 = (m1 < cnt);
        int   pid0 = 0, pid1 = 0;
        float pv0 = 0.f, pv1 = 0.f;
        if (v0) { pid0 = g_pairs[off + m0]; pv0 = expert_p[pid0]; }
        if (v1) { pid1 = g_pairs[off + m1]; pv1 = expert_p[pid1]; }
        float* dst0 = out + (size_t)(pid0 >> 1) * D_DIM;
        float* dst1 = out + (size_t)(pid1 >> 1) * D_DIM;
#pragma unroll
        for (int nt = 0; nt < 8; nt++) {
            int col = bn * 128 + wc * 64 + nt * 8 + 2 * (l & 3);
            if (v0) {
                atomicAdd(dst0 + col,     acc[mt][nt][0] * pv0);
                atomicAdd(dst0 + col + 1, acc[mt][nt][1] * pv0);
            }
            if (v1) {
                atomicAdd(dst1 + col,     acc[mt][nt][2] * pv1);
                atomicAdd(dst1 + col + 1, acc[mt][nt][3] * pv1);
            }
        }
    }
}

// ---------------------------------------------------------------------------
extern "C" void kernel_launch(void* const* d_in, const int* in_sizes, int n_in,
                              void* d_out, int out_size) {
    const float* x    = (const float*)d_in[0];
    const float* ep   = (const float*)d_in[1];
    const int*   eidx = (const int*)  d_in[2];
    const float* W1   = (const float*)d_in[3];
    const float* W2   = (const float*)d_in[4];
    float*       out  = (float*)d_out;

    cudaFuncSetAttribute(gemm1_mma, cudaFuncAttributeMaxDynamicSharedMemorySize, SMEM_DYN);
    cudaFuncSetAttribute(gemm2_mma, cudaFuncAttributeMaxDynamicSharedMemorySize, SMEM_DYN);

    bucket_kernel<<<1, 512>>>(eidx);
    zero_out_kernel<<<(NTOK * D_DIM / 4) / 256, 256>>>(out);

    int x8 = NTOK * D_DIM / 8;
    conv_x_kernel<<<x8 / 256, 256>>>(x);
    int w1_8 = E_NUM * D_DIM * H2 / 8;
    conv_w1_kernel<<<w1_8 / 256, 256>>>(W1);
    int w2_8 = E_NUM * H_DIM * D_DIM / 8;
    conv_w2_kernel<<<w2_8 / 256, 256>>>(W2);

    dim3 g1(H_DIM / 64, NPAIR / 128, E_NUM);    // (16, 32, 8)
    gemm1_mma<<<g1, 256, SMEM_DYN>>>();

    dim3 g2(D_DIM / 128, NPAIR / 128, E_NUM);   // (8, 32, 8)
    gemm2_mma<<<g2, 256, SMEM_DYN>>>(ep, out);
}

// round 12
// speedup vs baseline: 2.3649x; 1.0446x over previous
#include <cuda_runtime.h>
#include <cuda_fp16.h>
#include <cstdint>
#include <math.h>

#define E_NUM 8
#define D_DIM 1024
#define H_DIM 1024
#define H2    2048
#define NTOK  2048
#define NPAIR 4096

// ----------------------------- scratch globals ------------------------------
__device__ int g_pairs[NPAIR];
__device__ int g_cnt[E_NUM];
__device__ int g_off[E_NUM];
__device__ __half g_x[(size_t)NTOK * D_DIM];                // by TOKEN
__device__ __half g_w1_hi[(size_t)E_NUM * D_DIM * H2];      // [E][k=D][n=2H]
__device__ __half g_w2_hi[(size_t)E_NUM * H_DIM * D_DIM];   // [E][k=H][n=D]
__device__ __half g_act[(size_t)NPAIR * H_DIM];             // by sorted SLOT

// ------------------------------ helpers -------------------------------------
__device__ __forceinline__ uint32_t smem_u32(const void* p) {
    uint32_t a;
    asm("{ .reg .u64 t; cvta.to.shared.u64 t, %1; cvt.u32.u64 %0, t; }"
        : "=r"(a) : "l"(p));
    return a;
}
__device__ __forceinline__ void cp16(uint32_t dst, const void* src) {
    asm volatile("cp.async.cg.shared.global [%0], [%1], 16;"
                 :: "r"(dst), "l"(src) : "memory");
}
#define CP_COMMIT() asm volatile("cp.async.commit_group;" ::: "memory")
#define CP_WAIT(n)  asm volatile("cp.async.wait_group %0;" :: "n"(n) : "memory")

__device__ __forceinline__ void ldsm4(uint32_t* r, uint32_t a) {
    asm volatile("ldmatrix.sync.aligned.m8n8.x4.shared.b16 {%0,%1,%2,%3}, [%4];"
                 : "=r"(r[0]), "=r"(r[1]), "=r"(r[2]), "=r"(r[3]) : "r"(a));
}
__device__ __forceinline__ void ldsm4t(uint32_t* r, uint32_t a) {
    asm volatile("ldmatrix.sync.aligned.m8n8.x4.trans.shared.b16 {%0,%1,%2,%3}, [%4];"
                 : "=r"(r[0]), "=r"(r[1]), "=r"(r[2]), "=r"(r[3]) : "r"(a));
}
__device__ __forceinline__ void mma16816(float* d, const uint32_t* a, const uint32_t* b) {
    asm volatile(
        "mma.sync.aligned.m16n8k16.row.col.f32.f16.f16.f32 "
        "{%0,%1,%2,%3}, {%4,%5,%6,%7}, {%8,%9}, {%0,%1,%2,%3};"
        : "+f"(d[0]), "+f"(d[1]), "+f"(d[2]), "+f"(d[3])
        : "r"(a[0]), "r"(a[1]), "r"(a[2]), "r"(a[3]), "r"(b[0]), "r"(b[1]));
}
__device__ __forceinline__ uint32_t pack_h2(__half a, __half b) {
    return ((uint32_t)__half_as_ushort(b) << 16) | (uint32_t)__half_as_ushort(a);
}
__device__ __forceinline__ float silu_mul(float h, float g) {
    return h * (g / (1.f + __expf(-g)));
}

// SMEM: rows_s[128] ints @0; stages @512.
// Stage (K-chunk 64): A [128m][64k] pitch 144 | B [64k][128n] pitch 272. 3 stages.
#define A_PITCH  144
#define B_PITCH  272
#define OFF_A    0
#define OFF_B    (128 * A_PITCH)
#define STAGE_SZ (128 * A_PITCH + 64 * B_PITCH)     // 35840
#define NSTAGE   3
#define SMEM_DYN (512 + NSTAGE * STAGE_SZ)          // 108032 (x2 CTAs = 216KB/SM)
#define KCH      64
#define NITER    (D_DIM / KCH)                      // 16 (same for H_DIM)

// ---------------------------------------------------------------------------
// Kernel 0: bucket pairs by expert (single CTA)
// ---------------------------------------------------------------------------
__global__ void bucket_kernel(const int* __restrict__ expert_idxs) {
    __shared__ int scnt[E_NUM];
    __shared__ int soff[E_NUM];
    __shared__ int spos[E_NUM];
    int tid = threadIdx.x;
    if (tid < E_NUM) scnt[tid] = 0;
    __syncthreads();
    for (int i = tid; i < NPAIR; i += blockDim.x)
        atomicAdd(&scnt[expert_idxs[i]], 1);
    __syncthreads();
    if (tid == 0) {
        int s = 0;
        for (int e = 0; e < E_NUM; e++) { soff[e] = s; spos[e] = s; s += scnt[e]; }
    }
    __syncthreads();
    for (int i = tid; i < NPAIR; i += blockDim.x) {
        int e = expert_idxs[i];
        int pos = atomicAdd(&spos[e], 1);
        g_pairs[pos] = i;
    }
    __syncthreads();
    if (tid < E_NUM) { g_cnt[tid] = scnt[tid]; g_off[tid] = soff[tid]; }
}

// ---------------------------------------------------------------------------
// Kernel 1: zero the output (poisoned by harness; atomics accumulate into it)
// ---------------------------------------------------------------------------
__global__ void zero_out_kernel(float* __restrict__ out) {
    int q = blockIdx.x * blockDim.x + threadIdx.x;
    ((float4*)out)[q] = make_float4(0.f, 0.f, 0.f, 0.f);
}

// ---------------------------------------------------------------------------
// Kernel 2: fused fp32->fp16 conversion of x, W1, W2 (8 floats / thread)
//   idx ranges: [0, X8) -> x; [X8, X8+W18) -> W1; rest -> W2
// ---------------------------------------------------------------------------
#define X8   (NTOK * D_DIM / 8)                     // 262144
#define W18  (E_NUM * D_DIM * H2 / 8)               // 2097152
#define W28  (E_NUM * H_DIM * D_DIM / 8)            // 1048576
#define CONV_TOTAL (X8 + W18 + W28)                 // 3407872

__global__ void conv_all_kernel(const float* __restrict__ x,
                                const float* __restrict__ W1,
                                const float* __restrict__ W2) {
    int idx = blockIdx.x * blockDim.x + threadIdx.x;
    const float4* src;
    __half* dst;
    if (idx < X8) {
        src = (const float4*)x + (size_t)idx * 2;
        dst = g_x + (size_t)idx * 8;
    } else if (idx < X8 + W18) {
        int j = idx - X8;
        src = (const float4*)W1 + (size_t)j * 2;
        dst = g_w1_hi + (size_t)j * 8;
    } else {
        int j = idx - (X8 + W18);
        src = (const float4*)W2 + (size_t)j * 2;
        dst = g_w2_hi + (size_t)j * 8;
    }
    float4 a = src[0], b = src[1];
    uint4 o;
    o.x = pack_h2(__float2half_rn(a.x), __float2half_rn(a.y));
    o.y = pack_h2(__float2half_rn(a.z), __float2half_rn(a.w));
    o.z = pack_h2(__float2half_rn(b.x), __float2half_rn(b.y));
    o.w = pack_h2(__float2half_rn(b.z), __float2half_rn(b.w));
    *(uint4*)dst = o;
}

// ---------------------------------------------------------------------------
// GEMM1 (mma.sync fp16, occ=2, K-chunk 64, single-barrier pipeline)
//   act = h * silu(g).  CTA 128 x (64h+64g). grid = (H/64, NPAIR/128, E)
// ---------------------------------------------------------------------------
__global__ void __launch_bounds__(256, 2) gemm1_mma() {
    extern __shared__ char smem[];
    const int e   = blockIdx.z;
    const int bn  = blockIdx.x;
    const int bm  = blockIdx.y;
    const int cnt = g_cnt[e];
    if (bm * 128 >= cnt) return;
    const int off = g_off[e];
    const int tid = threadIdx.x;
    const int wid = tid >> 5;
    const int l   = tid & 31;
    const int wm  = wid >> 1;
    const int wc  = wid & 1;

    int* rows_s = (int*)smem;
    const uint32_t sbase = smem_u32(smem) + 512;

    if (tid < 128) {
        int m = bm * 128 + tid;
        rows_s[tid] = (m < cnt) ? (g_pairs[off + m] >> 1) : 0;
    }
    __syncthreads();

    uint32_t a_base[2];
#pragma unroll
    for (int mt = 0; mt < 2; mt++)
        a_base[mt] = (wm * 32 + mt * 16 + (l & 15)) * A_PITCH + (l >> 4) * 16;
    uint32_t b_base[4];
#pragma unroll
    for (int p = 0; p < 4; p++) {
        int colbase = (p < 2) ? (wc * 32 + p * 16) : (64 + wc * 32 + (p - 2) * 16);
        b_base[p] = (l & 15) * B_PITCH + (colbase + (l >> 4) * 8) * 2;
    }

    float acc[2][8][4];
#pragma unroll
    for (int mt = 0; mt < 2; mt++)
#pragma unroll
        for (int nt = 0; nt < 8; nt++)
#pragma unroll
            for (int i = 0; i < 4; i++) acc[mt][nt][i] = 0.f;

    auto load_stage = [&](int c, int buf) {
        const int kt = c * KCH;
        const uint32_t st = sbase + buf * STAGE_SZ;
#pragma unroll
        for (int i = 0; i < 4; i++) {
            int q = tid + i * 256;
            int r = q >> 3, ch = q & 7;
            cp16(st + OFF_A + r * A_PITCH + ch * 16,
                 g_x + (size_t)rows_s[r] * D_DIM + kt + ch * 8);
        }
#pragma unroll
        for (int i = 0; i < 4; i++) {
            int q = tid + i * 256;
            int r = q >> 4, ch = q & 15;
            int gcol = (ch < 8) ? (bn * 64 + ch * 8) : (H_DIM + bn * 64 + (ch - 8) * 8);
            cp16(st + OFF_B + r * B_PITCH + ch * 16,
                 g_w1_hi + ((size_t)e * D_DIM + kt + r) * H2 + gcol);
        }
        CP_COMMIT();
    };

    load_stage(0, 0);
    load_stage(1, 1);

    for (int c = 0; c < NITER; c++) {
        if (c == NITER - 1) { CP_WAIT(0); } else { CP_WAIT(1); }
        __syncthreads();                       // single barrier per iteration
        if (c < NITER - 2) load_stage(c + 2, (c + 2) % NSTAGE);
        const uint32_t st = sbase + (c % NSTAGE) * STAGE_SZ;
#pragma unroll
        for (int kk = 0; kk < 4; kk++) {
            uint32_t ah[2][4], bf[4][4];
#pragma unroll
            for (int mt = 0; mt < 2; mt++)
                ldsm4(ah[mt], st + OFF_A + a_base[mt] + kk * 32);
#pragma unroll
            for (int p = 0; p < 4; p++)
                ldsm4t(bf[p], st + OFF_B + b_base[p] + kk * (16 * B_PITCH));
#pragma unroll
            for (int mt = 0; mt < 2; mt++)
#pragma unroll
                for (int nt = 0; nt < 8; nt++)
                    mma16816(acc[mt][nt], ah[mt], &bf[nt >> 1][(nt & 1) * 2]);
        }
    }

    // ---- epilogue: pair h (nt) with g (nt+4), SiLU-GLU, store fp16 ----
#pragma unroll
    for (int mt = 0; mt < 2; mt++) {
        int m0 = bm * 128 + wm * 32 + mt * 16 + (l >> 2);
        int m1 = m0 + 8;
        bool v0 = (m0 < cnt), v1 = (m1 < cnt);
        size_t row0 = (size_t)(off + m0) * H_DIM;
        size_t row1 = (size_t)(off + m1) * H_DIM;
#pragma unroll
        for (int nt = 0; nt < 4; nt++) {
            int col = bn * 64 + wc * 32 + nt * 8 + 2 * (l & 3);
            float a0 = silu_mul(acc[mt][nt][0], acc[mt][nt + 4][0]);
            float a1 = silu_mul(acc[mt][nt][1], acc[mt][nt + 4][1]);
            float a2 = silu_mul(acc[mt][nt][2], acc[mt][nt + 4][2]);
            float a3 = silu_mul(acc[mt][nt][3], acc[mt][nt + 4][3]);
            if (v0)
                *(uint32_t*)(g_act + row0 + col) =
                    pack_h2(__float2half_rn(a0), __float2half_rn(a1));
            if (v1)
                *(uint32_t*)(g_act + row1 + col) =
                    pack_h2(__float2half_rn(a2), __float2half_rn(a3));
        }
    }
}

// ---------------------------------------------------------------------------
// GEMM2 (mma.sync fp16, occ=2, K-chunk 64, single-barrier pipeline)
//   out += (act @ W2) * p (atomic; exactly 2 contributions per element).
//   grid = (D/128, NPAIR/128, E)
// ---------------------------------------------------------------------------
__global__ void __launch_bounds__(256, 2) gemm2_mma(const float* __restrict__ expert_p,
                                                    float* __restrict__ out) {
    extern __shared__ char smem[];
    const int e   = blockIdx.z;
    const int bn  = blockIdx.x;
    const int bm  = blockIdx.y;
    const int cnt = g_cnt[e];
    if (bm * 128 >= cnt) return;
    const int off = g_off[e];
    const int tid = threadIdx.x;
    const int wid = tid >> 5;
    const int l   = tid & 31;
    const int wm  = wid >> 1;
    const int wc  = wid & 1;

    const uint32_t sbase = smem_u32(smem) + 512;

    uint32_t a_base[2];
#pragma unroll
    for (int mt = 0; mt < 2; mt++)
        a_base[mt] = (wm * 32 + mt * 16 + (l & 15)) * A_PITCH + (l >> 4) * 16;
    uint32_t b_base[4];
#pragma unroll
    for (int p = 0; p < 4; p++) {
        int colbase = wc * 64 + p * 16;
        b_base[p] = (l & 15) * B_PITCH + (colbase + (l >> 4) * 8) * 2;
    }

    float acc[2][8][4];
#pragma unroll
    for (int mt = 0; mt < 2; mt++)
#pragma unroll
        for (int nt = 0; nt < 8; nt++)
#pragma unroll
            for (int i = 0; i < 4; i++) acc[mt][nt][i] = 0.f;

    auto load_stage = [&](int c, int buf) {
        const int kt = c * KCH;
        const uint32_t st = sbase + buf * STAGE_SZ;
#pragma unroll
        for (int i = 0; i < 4; i++) {
            int q = tid + i * 256;
            int r = q >> 3, ch = q & 7;
            int gr = off + bm * 128 + r;
            if (gr > NPAIR - 1) gr = NPAIR - 1;
            cp16(st + OFF_A + r * A_PITCH + ch * 16,
                 g_act + (size_t)gr * H_DIM + kt + ch * 8);
        }
#pragma unroll
        for (int i = 0; i < 4; i++) {
            int q = tid + i * 256;
            int r = q >> 4, ch = q & 15;
            cp16(st + OFF_B + r * B_PITCH + ch * 16,
                 g_w2_hi + ((size_t)e * H_DIM + kt + r) * D_DIM + bn * 128 + ch * 8);
        }
        CP_COMMIT();
    };

    load_stage(0, 0);
    load_stage(1, 1);

    for (int c = 0; c < NITER; c++) {
        if (c == NITER - 1) { CP_WAIT(0); } else { CP_WAIT(1); }
        __syncthreads();
        if (c < NITER - 2) load_stage(c + 2, (c + 2) % NSTAGE);
        const uint32_t st = sbase + (c % NSTAGE) * STAGE_SZ;
#pragma unroll
        for (int kk = 0; kk < 4; kk++) {
            uint32_t ah[2][4], bf[4][4];
#pragma unroll
            for (int mt = 0; mt < 2; mt++)
                ldsm4(ah[mt], st + OFF_A + a_base[mt] + kk * 32);
#pragma unroll
            for (int p = 0; p < 4; p++)
                ldsm4t(bf[p], st + OFF_B + b_base[p] + kk * (16 * B_PITCH));
#pragma unroll
            for (int mt = 0; mt < 2; mt++)
#pragma unroll
                for (int nt = 0; nt < 8; nt++)
                    mma16816(acc[mt][nt], ah[mt], &bf[nt >> 1][(nt & 1) * 2]);
        }
    }

    // ---- epilogue: scale by gate prob, atomically accumulate into out ----
#pragma unroll
    for (int mt = 0; mt < 2; mt++) {
        int m0 = bm * 128 + wm * 32 + mt * 16 + (l >> 2);
        int m1 = m0 + 8;
        bool v0 = (m0 < cnt), v1 = (m1 < cnt);
        int   pid0 = 0, pid1 = 0;
        float pv0 = 0.f, pv1 = 0.f;
        if (v0) { pid0 = g_pairs[off + m0]; pv0 = expert_p[pid0]; }
        if (v1) { pid1 = g_pairs[off + m1]; pv1 = expert_p[pid1]; }
        float* dst0 = out + (size_t)(pid0 >> 1) * D_DIM;
        float* dst1 = out + (size_t)(pid1 >> 1) * D_DIM;
#pragma unroll
        for (int nt = 0; nt < 8; nt++) {
            int col = bn * 128 + wc * 64 + nt * 8 + 2 * (l & 3);
            if (v0) {
                atomicAdd(dst0 + col,     acc[mt][nt][0] * pv0);
                atomicAdd(dst0 + col + 1, acc[mt][nt][1] * pv0);
            }
            if (v1) {
                atomicAdd(dst1 + col,     acc[mt][nt][2] * pv1);
                atomicAdd(dst1 + col + 1, acc[mt][nt][3] * pv1);
            }
        }
    }
}

// ---------------------------------------------------------------------------
extern "C" void kernel_launch(void* const* d_in, const int* in_sizes, int n_in,
                              void* d_out, int out_size) {
    const float* x    = (const float*)d_in[0];
    const float* ep   = (const float*)d_in[1];
    const int*   eidx = (const int*)  d_in[2];
    const float* W1   = (const float*)d_in[3];
    const float* W2   = (const float*)d_in[4];
    float*       out  = (float*)d_out;

    cudaFuncSetAttribute(gemm1_mma, cudaFuncAttributeMaxDynamicSharedMemorySize, SMEM_DYN);
    cudaFuncSetAttribute(gemm2_mma, cudaFuncAttributeMaxDynamicSharedMemorySize, SMEM_DYN);

    bucket_kernel<<<1, 512>>>(eidx);
    zero_out_kernel<<<(NTOK * D_DIM / 4) / 256, 256>>>(out);

    conv_all_kernel<<<CONV_TOTAL / 256, 256>>>(x, W1, W2);

    dim3 g1(H_DIM / 64, NPAIR / 128, E_NUM);    // (16, 32, 8)
    gemm1_mma<<<g1, 256, SMEM_DYN>>>();

    dim3 g2(D_DIM / 128, NPAIR / 128, E_NUM);   // (8, 32, 8)
    gemm2_mma<<<g2, 256, SMEM_DYN>>>(ep, out);
}